// round 3
// baseline (speedup 1.0000x reference)
#include <cuda_runtime.h>
#include <math.h>

#define NN 50000
#define NE 800000
#define D  64
#define NG 128
#define DH 32
#define NC 6

// ---------------- scratch (device globals; no allocation allowed) ----------
__device__ float g_h[NN * D];       // hidden state
__device__ float g_m[NN * D];       // per-node messages m = h @ W[l]
__device__ float g_agg[NN * D];     // scatter-add destination
__device__ float g_pooled[NG * D];  // graph pooling sums
__device__ int   g_cnt[NG];         // nodes per graph

__device__ __forceinline__ float sigf(float x) {
    return __fdividef(1.f, 1.f + __expf(-x));
}
__device__ __forceinline__ float tanhfast(float x) {
    return __fdividef(2.f, 1.f + __expf(-2.f * x)) - 1.f;
}

// ---------------- init: zero pooled sums + counts ---------------------------
__global__ void k_init() {
    int t = threadIdx.x;
    for (int i = t; i < NG * D; i += 256) g_pooled[i] = 0.f;
    if (t < NG) g_cnt[t] = 0;
}

// ---------------- per-graph node counts -------------------------------------
__global__ void k_count(const int* __restrict__ batch) {
    int n = blockIdx.x * 256 + threadIdx.x;
    if (n < NN) atomicAdd(&g_cnt[batch[n]], 1);
}

// ---------------- m = h @ W[layer]; also zeroes agg -------------------------
// 256 threads: thread owns output dim d = tid&63 for 4 nodes of a 16-node chunk.
// W column (64 floats) register-resident; h rows staged to smem (broadcast LDS).
__global__ void k_mgemm(const float* __restrict__ x, const float* __restrict__ W,
                        int layer) {
    __shared__ float hs[16 * D];
    const float* hin = layer ? g_h : x;
    const float* Wl  = W + layer * D * D;

    int tid = threadIdx.x;
    int d   = tid & 63;
    int ns  = tid >> 6;  // 0..3

    float wcol[64];
#pragma unroll
    for (int k = 0; k < 64; k++) wcol[k] = Wl[k * 64 + d];

    for (int chunk = blockIdx.x * 16; chunk < NN; chunk += gridDim.x * 16) {
        __syncthreads();
#pragma unroll
        for (int i = 0; i < 4; i++) {
            int idx = tid + i * 256;  // 1024 floats = 16 rows
            hs[idx] = hin[chunk * 64 + idx];
        }
        __syncthreads();

        float acc0 = 0.f, acc1 = 0.f, acc2 = 0.f, acc3 = 0.f;
        const float4* h4_0 = reinterpret_cast<const float4*>(&hs[(ns + 0) * 64]);
        const float4* h4_1 = reinterpret_cast<const float4*>(&hs[(ns + 4) * 64]);
        const float4* h4_2 = reinterpret_cast<const float4*>(&hs[(ns + 8) * 64]);
        const float4* h4_3 = reinterpret_cast<const float4*>(&hs[(ns + 12) * 64]);
#pragma unroll
        for (int k4 = 0; k4 < 16; k4++) {
            float4 a = h4_0[k4], b = h4_1[k4], c = h4_2[k4], e = h4_3[k4];
            float w0 = wcol[k4 * 4 + 0], w1 = wcol[k4 * 4 + 1];
            float w2 = wcol[k4 * 4 + 2], w3 = wcol[k4 * 4 + 3];
            acc0 += a.x * w0 + a.y * w1 + a.z * w2 + a.w * w3;
            acc1 += b.x * w0 + b.y * w1 + b.z * w2 + b.w * w3;
            acc2 += c.x * w0 + c.y * w1 + c.z * w2 + c.w * w3;
            acc3 += e.x * w0 + e.y * w1 + e.z * w2 + e.w * w3;
        }
        int n0 = chunk + ns;
        g_m[(n0 + 0) * 64 + d]  = acc0;
        g_m[(n0 + 4) * 64 + d]  = acc1;
        g_m[(n0 + 8) * 64 + d]  = acc2;
        g_m[(n0 + 12) * 64 + d] = acc3;
        g_agg[(n0 + 0) * 64 + d]  = 0.f;
        g_agg[(n0 + 4) * 64 + d]  = 0.f;
        g_agg[(n0 + 8) * 64 + d]  = 0.f;
        g_agg[(n0 + 12) * 64 + d] = 0.f;
    }
}

// ---------------- edge scatter: agg[dst] += m[src] --------------------------
// One thread per (edge, 16B quad): float4 gather from L2-resident m,
// 128-bit vector atomic into agg (sm_90+ atomicAdd(float4*)).
__global__ void k_scatter(const int* __restrict__ ei) {
    int t = blockIdx.x * 256 + threadIdx.x;
    if (t >= NE * 16) return;
    int e = t >> 4;
    int q = t & 15;
    int src = ei[e];
    int dst = ei[NE + e];
    float4 v = *reinterpret_cast<const float4*>(&g_m[src * 64 + q * 4]);
    atomicAdd(reinterpret_cast<float4*>(&g_agg[dst * 64 + q * 4]), v);
}

// ---------------- fused GRU cell (+ relu/pool epilogue on last layer) -------
// 256 threads; weights transposed into smem once per block (conflict-free LDS:
// consecutive d -> consecutive addrs). Thread owns dim d for 4 nodes of each
// 16-node chunk; agg/h rows staged to smem (pure broadcast reads).
#define GRU_SMEM ((2 * 64 * 192 + 2 * 16 * 64 + 2 * 192) * 4)

__global__ void k_gru(const float* __restrict__ x,
                      const float* __restrict__ w_ih, const float* __restrict__ w_hh,
                      const float* __restrict__ b_ih, const float* __restrict__ b_hh,
                      const int* __restrict__ batch, int layer) {
    extern __shared__ float sm[];
    float* wiT  = sm;                 // [64][192]  wiT[k*192+r] = w_ih[r][k]
    float* whT  = wiT + 64 * 192;     // [64][192]
    float* aggs = whT + 64 * 192;     // [16][64]
    float* hs   = aggs + 16 * 64;     // [16][64]
    float* bi   = hs + 16 * 64;       // [192]
    float* bh   = bi + 192;           // [192]

    int tid = threadIdx.x;
    for (int i = tid; i < 192 * 64; i += 256) {
        int r = i >> 6, k = i & 63;
        wiT[k * 192 + r] = w_ih[i];
        whT[k * 192 + r] = w_hh[i];
    }
    if (tid < 192) { bi[tid] = b_ih[tid]; bh[tid] = b_hh[tid]; }

    const float* hin = layer ? g_h : x;
    int d  = tid & 63;
    int ns = tid >> 6;  // 0..3  (constant within a warp -> broadcast LDS)

    for (int chunk = blockIdx.x * 16; chunk < NN; chunk += gridDim.x * 16) {
        __syncthreads();
#pragma unroll
        for (int i = 0; i < 4; i++) {
            int idx = tid + i * 256;
            aggs[idx] = g_agg[chunk * 64 + idx];
            hs[idx]   = hin[chunk * 64 + idx];
        }
        __syncthreads();

        float ir[4] = {0, 0, 0, 0}, iz[4] = {0, 0, 0, 0}, ix[4] = {0, 0, 0, 0};
        float hr[4] = {0, 0, 0, 0}, hz[4] = {0, 0, 0, 0}, hn[4] = {0, 0, 0, 0};
#pragma unroll 16
        for (int k = 0; k < 64; k++) {
            float wr = wiT[k * 192 + d];
            float wz = wiT[k * 192 + 64 + d];
            float wn = wiT[k * 192 + 128 + d];
            float ur = whT[k * 192 + d];
            float uz = whT[k * 192 + 64 + d];
            float un = whT[k * 192 + 128 + d];
#pragma unroll
            for (int j = 0; j < 4; j++) {
                float a  = aggs[(ns + 4 * j) * 64 + k];
                float hh = hs[(ns + 4 * j) * 64 + k];
                ir[j] += a * wr;  iz[j] += a * wz;  ix[j] += a * wn;
                hr[j] += hh * ur; hz[j] += hh * uz; hn[j] += hh * un;
            }
        }

#pragma unroll
        for (int j = 0; j < 4; j++) {
            int n = chunk + ns + 4 * j;
            float r  = sigf(ir[j] + bi[d] + hr[j] + bh[d]);
            float z  = sigf(iz[j] + bi[64 + d] + hz[j] + bh[64 + d]);
            float nn = tanhfast(ix[j] + bi[128 + d] + r * (hn[j] + bh[128 + d]));
            float ho = hs[(ns + 4 * j) * 64 + d];
            float hv = (1.f - z) * nn + z * ho;
            if (layer == 0) {
                g_h[n * 64 + d] = hv;
            } else {
                float rv = fmaxf(hv, 0.f);
                atomicAdd(&g_pooled[batch[n] * 64 + d], rv);
            }
        }
    }
}

// ---------------- mean pool + fc1(relu) + fc2 + log_softmax -----------------
__global__ void k_poolfc(const float* __restrict__ fc1w, const float* __restrict__ fc1b,
                         const float* __restrict__ fc2w, const float* __restrict__ fc2b,
                         float* __restrict__ out) {
    int g = threadIdx.x;
    if (g >= NG) return;
    float inv = 1.f / fmaxf((float)g_cnt[g], 1.f);
    float p[D];
#pragma unroll
    for (int k = 0; k < D; k++) p[k] = g_pooled[g * D + k] * inv;

    float y[DH];
#pragma unroll
    for (int j = 0; j < DH; j++) {
        float s = fc1b[j];
#pragma unroll
        for (int k = 0; k < D; k++) s += p[k] * fc1w[j * D + k];
        y[j] = fmaxf(s, 0.f);
    }

    float z[NC];
    float mx = -1e30f;
#pragma unroll
    for (int c = 0; c < NC; c++) {
        float s = fc2b[c];
#pragma unroll
        for (int j = 0; j < DH; j++) s += y[j] * fc2w[c * DH + j];
        z[c] = s;
        mx = fmaxf(mx, s);
    }
    float lse = 0.f;
#pragma unroll
    for (int c = 0; c < NC; c++) lse += expf(z[c] - mx);
    lse = logf(lse) + mx;
#pragma unroll
    for (int c = 0; c < NC; c++) out[g * NC + c] = z[c] - lse;
}

// ---------------- launch -----------------------------------------------------
extern "C" void kernel_launch(void* const* d_in, const int* in_sizes, int n_in,
                              void* d_out, int out_size) {
    const float* x     = (const float*)d_in[0];
    const int*   ei    = (const int*)d_in[1];
    const int*   batch = (const int*)d_in[2];
    const float* W     = (const float*)d_in[3];
    const float* w_ih  = (const float*)d_in[4];
    const float* w_hh  = (const float*)d_in[5];
    const float* b_ih  = (const float*)d_in[6];
    const float* b_hh  = (const float*)d_in[7];
    const float* fc1w  = (const float*)d_in[8];
    const float* fc1b  = (const float*)d_in[9];
    const float* fc2w  = (const float*)d_in[10];
    const float* fc2b  = (const float*)d_in[11];
    float* out = (float*)d_out;

    cudaFuncSetAttribute(k_gru, cudaFuncAttributeMaxDynamicSharedMemorySize, GRU_SMEM);

    k_init<<<1, 256>>>();
    k_count<<<(NN + 255) / 256, 256>>>(batch);

    for (int l = 0; l < 2; l++) {
        k_mgemm<<<592, 256>>>(x, W, l);
        k_scatter<<<(NE * 16) / 256, 256>>>(ei);
        k_gru<<<296, 256, GRU_SMEM>>>(x, w_ih, w_hh, b_ih, b_hh, batch, l);
    }
    k_poolfc<<<1, 128>>>(fc1w, fc1b, fc2w, fc2b, out);
}

// round 4
// speedup vs baseline: 1.4302x; 1.4302x over previous
#include <cuda_runtime.h>
#include <cuda_bf16.h>
#include <math.h>

#define NN 50000
#define NE 800000
#define D  64
#define NG 128
#define DH 32
#define NC 6

// ---------------- scratch (device globals; no allocation allowed) ----------
__device__ float g_h[NN * D];       // hidden state
__device__ float g_m[NN * D];       // per-node messages m = h @ W[l]
__device__ float g_agg[NN * D];     // scatter-add destination
__device__ float g_pooled[NG * D];  // graph pooling sums
__device__ int   g_cnt[NG];         // nodes per graph

__device__ __forceinline__ float sigf(float x) {
    return __fdividef(1.f, 1.f + __expf(-x));
}
__device__ __forceinline__ float tanhfast(float x) {
    return __fdividef(2.f, 1.f + __expf(-2.f * x)) - 1.f;
}

// bf16 split helpers: v = hi + lo with |residual| ~ 2^-16 |v|
__device__ __forceinline__ void split1(float v, __nv_bfloat16& h, __nv_bfloat16& l) {
    h = __float2bfloat16(v);
    l = __float2bfloat16(v - __bfloat162float(h));
}
__device__ __forceinline__ void split_pair(float v0, float v1, unsigned& hi, unsigned& lo) {
    __nv_bfloat16 h0, l0, h1, l1;
    split1(v0, h0, l0);
    split1(v1, h1, l1);
    hi = (unsigned)__bfloat16_as_ushort(h0) | ((unsigned)__bfloat16_as_ushort(h1) << 16);
    lo = (unsigned)__bfloat16_as_ushort(l0) | ((unsigned)__bfloat16_as_ushort(l1) << 16);
}

// mma.sync m16n8k16 bf16 -> f32 accumulate
__device__ __forceinline__ void mma16816(float* c, const unsigned* a, const unsigned* b) {
    asm volatile(
        "mma.sync.aligned.m16n8k16.row.col.f32.bf16.bf16.f32 "
        "{%0,%1,%2,%3}, {%4,%5,%6,%7}, {%8,%9}, {%0,%1,%2,%3};"
        : "+f"(c[0]), "+f"(c[1]), "+f"(c[2]), "+f"(c[3])
        : "r"(a[0]), "r"(a[1]), "r"(a[2]), "r"(a[3]), "r"(b[0]), "r"(b[1]));
}

// ---------------- init: zero pooled sums + counts ---------------------------
__global__ void k_init() {
    int t = threadIdx.x;
    for (int i = t; i < NG * D; i += 256) g_pooled[i] = 0.f;
    if (t < NG) g_cnt[t] = 0;
}

// ---------------- per-graph node counts -------------------------------------
__global__ void k_count(const int* __restrict__ batch) {
    int n = blockIdx.x * 256 + threadIdx.x;
    if (n < NN) atomicAdd(&g_cnt[batch[n]], 1);
}

// ---------------- m = h @ W[layer] via bf16x3 tensor cores; zeroes agg ------
// 8 warps, warp w owns output dims [8w, 8w+8). 16-node M-tiles.
__global__ __launch_bounds__(256, 1)
void k_mgemm(const float* __restrict__ x, const float* __restrict__ W, int layer) {
    __shared__ __align__(16) __nv_bfloat16 s_hhi[16 * 72];
    __shared__ __align__(16) __nv_bfloat16 s_hlo[16 * 72];

    int tid = threadIdx.x;
    int wid = tid >> 5, lane = tid & 31;
    int tg = lane & 3, gid = lane >> 2;
    int dbase = wid * 8;
    int d0 = dbase + tg * 2;

    const float* Wl = W + layer * 64 * 64;
    // B[k][n] = Wl[k*64 + (dbase + gid)]
    unsigned Bhi[4][2], Blo[4][2];
#pragma unroll
    for (int kt = 0; kt < 4; kt++) {
        int k0 = kt * 16 + tg * 2;
        int nc = dbase + gid;
        split_pair(Wl[(k0)     * 64 + nc], Wl[(k0 + 1) * 64 + nc], Bhi[kt][0], Blo[kt][0]);
        split_pair(Wl[(k0 + 8) * 64 + nc], Wl[(k0 + 9) * 64 + nc], Bhi[kt][1], Blo[kt][1]);
    }

    const float* hin = layer ? g_h : x;

    for (int chunk = blockIdx.x * 16; chunk < NN; chunk += gridDim.x * 16) {
        __syncthreads();
#pragma unroll
        for (int i = 0; i < 4; i++) {
            int idx = tid + i * 256;
            int row = idx >> 6, col = idx & 63;
            float h = hin[chunk * 64 + idx];
            __nv_bfloat16 hh, ll;
            split1(h, hh, ll);
            s_hhi[row * 72 + col] = hh;
            s_hlo[row * 72 + col] = ll;
        }
        __syncthreads();

        float C[4] = {0.f, 0.f, 0.f, 0.f};
#pragma unroll
        for (int kt = 0; kt < 4; kt++) {
            int k0 = kt * 16 + tg * 2;
            unsigned ahi[4], alo[4];
            ahi[0] = *(const unsigned*)&s_hhi[(gid)     * 72 + k0];
            ahi[1] = *(const unsigned*)&s_hhi[(gid + 8) * 72 + k0];
            ahi[2] = *(const unsigned*)&s_hhi[(gid)     * 72 + k0 + 8];
            ahi[3] = *(const unsigned*)&s_hhi[(gid + 8) * 72 + k0 + 8];
            alo[0] = *(const unsigned*)&s_hlo[(gid)     * 72 + k0];
            alo[1] = *(const unsigned*)&s_hlo[(gid + 8) * 72 + k0];
            alo[2] = *(const unsigned*)&s_hlo[(gid)     * 72 + k0 + 8];
            alo[3] = *(const unsigned*)&s_hlo[(gid + 8) * 72 + k0 + 8];
            mma16816(C, ahi, Bhi[kt]);
            mma16816(C, ahi, Blo[kt]);
            mma16816(C, alo, Bhi[kt]);
        }

#pragma unroll
        for (int p = 0; p < 2; p++) {
            int node = chunk + gid + p * 8;
            float2 mv = make_float2(C[p * 2], C[p * 2 + 1]);
            *(float2*)&g_m[node * 64 + d0] = mv;
            *(float2*)&g_agg[node * 64 + d0] = make_float2(0.f, 0.f);
        }
    }
}

// ---------------- edge scatter: agg[dst] += m[src] --------------------------
__global__ void k_scatter(const int* __restrict__ ei) {
    int t = blockIdx.x * 256 + threadIdx.x;
    if (t >= NE * 16) return;
    int e = t >> 4;
    int q = t & 15;
    int src = ei[e];
    int dst = ei[NE + e];
    float4 v = *reinterpret_cast<const float4*>(&g_m[src * 64 + q * 4]);
    atomicAdd(reinterpret_cast<float4*>(&g_agg[dst * 64 + q * 4]), v);
}

// ---------------- fused GRU gates via bf16x3 tensor cores -------------------
// Warp w owns d-slice [8w, 8w+8) of ALL six gate blocks -> full GRU
// elementwise epilogue stays in C-fragment registers.
__global__ __launch_bounds__(256, 1)
void k_gates(const float* __restrict__ x,
             const float* __restrict__ w_ih, const float* __restrict__ w_hh,
             const float* __restrict__ b_ih, const float* __restrict__ b_hh,
             const int* __restrict__ batch, int layer) {
    __shared__ __align__(16) __nv_bfloat16 s_ahi[16 * 72];
    __shared__ __align__(16) __nv_bfloat16 s_alo[16 * 72];
    __shared__ __align__(16) __nv_bfloat16 s_hhi[16 * 72];
    __shared__ __align__(16) __nv_bfloat16 s_hlo[16 * 72];
    __shared__ __align__(16) float s_hf[16 * 66];

    int tid = threadIdx.x;
    int wid = tid >> 5, lane = tid & 31;
    int tg = lane & 3, gid = lane >> 2;
    int dbase = wid * 8;
    int d0 = dbase + tg * 2;

    // B fragments: gates 0..2 = w_ih rows, 3..5 = w_hh rows.
    // B[k][n] = wmat[(g%3)*64 + dbase + gid][k]
    unsigned Bhi[6][4][2], Blo[6][4][2];
#pragma unroll
    for (int g = 0; g < 6; g++) {
        const float* wm = (g < 3) ? w_ih : w_hh;
        const float* wr = wm + ((g % 3) * 64 + dbase + gid) * 64;
#pragma unroll
        for (int kt = 0; kt < 4; kt++) {
            int k0 = kt * 16 + tg * 2;
            split_pair(wr[k0],     wr[k0 + 1], Bhi[g][kt][0], Blo[g][kt][0]);
            split_pair(wr[k0 + 8], wr[k0 + 9], Bhi[g][kt][1], Blo[g][kt][1]);
        }
    }
    float bi0[2], bi1[2], bi2[2], bh0[2], bh1[2], bh2[2];
#pragma unroll
    for (int j = 0; j < 2; j++) {
        bi0[j] = b_ih[d0 + j];       bh0[j] = b_hh[d0 + j];
        bi1[j] = b_ih[64 + d0 + j];  bh1[j] = b_hh[64 + d0 + j];
        bi2[j] = b_ih[128 + d0 + j]; bh2[j] = b_hh[128 + d0 + j];
    }

    const float* hin = layer ? g_h : x;

    for (int chunk = blockIdx.x * 16; chunk < NN; chunk += gridDim.x * 16) {
        __syncthreads();
#pragma unroll
        for (int i = 0; i < 4; i++) {
            int idx = tid + i * 256;
            int row = idx >> 6, col = idx & 63;
            float a = g_agg[chunk * 64 + idx];
            float h = hin[chunk * 64 + idx];
            __nv_bfloat16 hh, ll;
            split1(a, hh, ll);
            s_ahi[row * 72 + col] = hh;
            s_alo[row * 72 + col] = ll;
            split1(h, hh, ll);
            s_hhi[row * 72 + col] = hh;
            s_hlo[row * 72 + col] = ll;
            s_hf[row * 66 + col] = h;
        }
        __syncthreads();

        float C[6][4];
#pragma unroll
        for (int g = 0; g < 6; g++)
#pragma unroll
            for (int q = 0; q < 4; q++) C[g][q] = 0.f;

#pragma unroll
        for (int kt = 0; kt < 4; kt++) {
            int k0 = kt * 16 + tg * 2;
            unsigned ahi[4], alo[4];
            // agg tile -> gates 0..2 (i_r, i_z, i_n)
            ahi[0] = *(const unsigned*)&s_ahi[(gid)     * 72 + k0];
            ahi[1] = *(const unsigned*)&s_ahi[(gid + 8) * 72 + k0];
            ahi[2] = *(const unsigned*)&s_ahi[(gid)     * 72 + k0 + 8];
            ahi[3] = *(const unsigned*)&s_ahi[(gid + 8) * 72 + k0 + 8];
            alo[0] = *(const unsigned*)&s_alo[(gid)     * 72 + k0];
            alo[1] = *(const unsigned*)&s_alo[(gid + 8) * 72 + k0];
            alo[2] = *(const unsigned*)&s_alo[(gid)     * 72 + k0 + 8];
            alo[3] = *(const unsigned*)&s_alo[(gid + 8) * 72 + k0 + 8];
#pragma unroll
            for (int g = 0; g < 3; g++) {
                mma16816(C[g], ahi, Bhi[g][kt]);
                mma16816(C[g], ahi, Blo[g][kt]);
                mma16816(C[g], alo, Bhi[g][kt]);
            }
            // h tile -> gates 3..5 (h_r, h_z, h_n)
            ahi[0] = *(const unsigned*)&s_hhi[(gid)     * 72 + k0];
            ahi[1] = *(const unsigned*)&s_hhi[(gid + 8) * 72 + k0];
            ahi[2] = *(const unsigned*)&s_hhi[(gid)     * 72 + k0 + 8];
            ahi[3] = *(const unsigned*)&s_hhi[(gid + 8) * 72 + k0 + 8];
            alo[0] = *(const unsigned*)&s_hlo[(gid)     * 72 + k0];
            alo[1] = *(const unsigned*)&s_hlo[(gid + 8) * 72 + k0];
            alo[2] = *(const unsigned*)&s_hlo[(gid)     * 72 + k0 + 8];
            alo[3] = *(const unsigned*)&s_hlo[(gid + 8) * 72 + k0 + 8];
#pragma unroll
            for (int g = 3; g < 6; g++) {
                mma16816(C[g], ahi, Bhi[g][kt]);
                mma16816(C[g], ahi, Blo[g][kt]);
                mma16816(C[g], alo, Bhi[g][kt]);
            }
        }

        // GRU elementwise epilogue (per-thread: 2 rows x 2 dims)
#pragma unroll
        for (int p = 0; p < 2; p++) {
            int row = gid + p * 8;
            int node = chunk + row;
#pragma unroll
            for (int j = 0; j < 2; j++) {
                int q = p * 2 + j;
                float r  = sigf(C[0][q] + bi0[j] + C[3][q] + bh0[j]);
                float z  = sigf(C[1][q] + bi1[j] + C[4][q] + bh1[j]);
                float nn = tanhfast(C[2][q] + bi2[j] + r * (C[5][q] + bh2[j]));
                float ho = s_hf[row * 66 + d0 + j];
                float hv = (1.f - z) * nn + z * ho;
                if (layer == 0) {
                    g_h[node * 64 + d0 + j] = hv;
                } else {
                    atomicAdd(&g_pooled[batch[node] * 64 + d0 + j], fmaxf(hv, 0.f));
                }
            }
        }
    }
}

// ---------------- mean pool + fc1(relu) + fc2 + log_softmax -----------------
__global__ void k_poolfc(const float* __restrict__ fc1w, const float* __restrict__ fc1b,
                         const float* __restrict__ fc2w, const float* __restrict__ fc2b,
                         float* __restrict__ out) {
    int g = threadIdx.x;
    if (g >= NG) return;
    float inv = 1.f / fmaxf((float)g_cnt[g], 1.f);
    float p[D];
#pragma unroll
    for (int k = 0; k < D; k++) p[k] = g_pooled[g * D + k] * inv;

    float y[DH];
#pragma unroll
    for (int j = 0; j < DH; j++) {
        float s = fc1b[j];
#pragma unroll
        for (int k = 0; k < D; k++) s += p[k] * fc1w[j * D + k];
        y[j] = fmaxf(s, 0.f);
    }

    float z[NC];
    float mx = -1e30f;
#pragma unroll
    for (int c = 0; c < NC; c++) {
        float s = fc2b[c];
#pragma unroll
        for (int j = 0; j < DH; j++) s += y[j] * fc2w[c * DH + j];
        z[c] = s;
        mx = fmaxf(mx, s);
    }
    float lse = 0.f;
#pragma unroll
    for (int c = 0; c < NC; c++) lse += expf(z[c] - mx);
    lse = logf(lse) + mx;
#pragma unroll
    for (int c = 0; c < NC; c++) out[g * NC + c] = z[c] - lse;
}

// ---------------- launch -----------------------------------------------------
extern "C" void kernel_launch(void* const* d_in, const int* in_sizes, int n_in,
                              void* d_out, int out_size) {
    const float* x     = (const float*)d_in[0];
    const int*   ei    = (const int*)d_in[1];
    const int*   batch = (const int*)d_in[2];
    const float* W     = (const float*)d_in[3];
    const float* w_ih  = (const float*)d_in[4];
    const float* w_hh  = (const float*)d_in[5];
    const float* b_ih  = (const float*)d_in[6];
    const float* b_hh  = (const float*)d_in[7];
    const float* fc1w  = (const float*)d_in[8];
    const float* fc1b  = (const float*)d_in[9];
    const float* fc2w  = (const float*)d_in[10];
    const float* fc2b  = (const float*)d_in[11];
    float* out = (float*)d_out;

    k_init<<<1, 256>>>();
    k_count<<<(NN + 255) / 256, 256>>>(batch);

    for (int l = 0; l < 2; l++) {
        k_mgemm<<<296, 256>>>(x, W, l);
        k_scatter<<<(NE * 16) / 256, 256>>>(ei);
        k_gates<<<296, 256>>>(x, w_ih, w_hh, b_ih, b_hh, batch, l);
    }
    k_poolfc<<<1, 128>>>(fc1w, fc1b, fc2w, fc2b, out);
}